// round 11
// baseline (speedup 1.0000x reference)
#include <cuda_runtime.h>
#include <math.h>
#include <stdint.h>

#define NN 32
#define MM 100
#define KK 500
#define EE 50
#define SU_C 1000.0f
#define SL_C 0.0f
#define TU_C 500.0f
#define TL_C 0.0f
#define R_EARTH_C 6371.0f
#define DEG2RAD 0.017453292519943295f

#define ROWS_PER_BLK 250                   // k-rows per block
#define CHUNKS 2                           // blocks per (n,m) tile
#define CHUNK_FLOATS (ROWS_PER_BLK * EE)   // 12500 floats = 3125 float4

__global__ __launch_bounds__(256) void embed_kernel(
    const int* __restrict__ traj_loc,   // (N, M)
    const float* __restrict__ poi,      // (LOC, 2)
    const float* __restrict__ vec,      // (N, M)
    const int* __restrict__ traj_len,   // (N,)
    const int* __restrict__ cand,       // (N, K)
    const float* __restrict__ emb_su,   // (2, E)
    const float* __restrict__ emb_sl,   // (2, E)
    const float* __restrict__ emb_tu,   // (2, E)
    const float* __restrict__ emb_tl,   // (2, E)
    float* __restrict__ out)            // (N, M, K, E)
{
    const int bid   = blockIdx.x;           // 0 .. N*M*CHUNKS-1
    const int nm    = bid >> 1;             // CHUNKS == 2
    const int chunk = bid & 1;
    const int n = nm / MM;
    const int m = nm - n * MM;
    const int tid = threadIdx.x;

    __shared__ float sC[EE];
    __shared__ float sB[EE];
    __shared__ __align__(8) float sds[ROWS_PER_BLK];

    // ---- per-(n,m) scalars ----
    const int loc1 = traj_loc[nm];
    const float2 p1 = ((const float2*)poi)[loc1];
    const float lat1 = p1.x * DEG2RAD;
    const float lon1 = p1.y * DEG2RAD;
    const float cos_lat1 = __cosf(lat1);

    const int maskv = (m < traj_len[n]) ? 1 : 0;
    const float dt = vec[nm];

    // ---- phase 1a: coefficients C[e], B[e] ----
    if (tid < EE) {
        const float esl = emb_sl[maskv * EE + tid];
        const float esu = emb_su[maskv * EE + tid];
        const float etl = emb_tl[maskv * EE + tid];
        const float etu = emb_tu[maskv * EE + tid];
        const float invS = 1.0f / (SU_C - SL_C);
        const float invT = 1.0f / (TU_C - TL_C);
        const float timev = (etl * (TU_C - dt) + etu * (dt - TL_C)) * invT;
        sC[tid] = (esl * SU_C - esu * SL_C) * invS + timev;
        sB[tid] = (esu - esl) * invS;
    }

    // ---- phase 1b: haversine for this chunk's 250 rows, all 8 warps ----
    if (tid < ROWS_PER_BLK) {
        const int k = chunk * ROWS_PER_BLK + tid;
        const int loc2 = cand[n * KK + k];
        const float2 p2 = ((const float2*)poi)[loc2];
        const float lat2 = p2.x * DEG2RAD;
        const float lon2 = p2.y * DEG2RAD;
        const float sdlat = __sinf((lat2 - lat1) * 0.5f);
        const float sdlon = __sinf((lon2 - lon1) * 0.5f);
        float a = sdlat * sdlat + cos_lat1 * __cosf(lat2) * (sdlon * sdlon);
        a = __saturatef(a);
        sds[tid] = 2.0f * R_EARTH_C * asinf(sqrtf(a));
    }
    __syncthreads();

    // ---- phase 2: outer-product write, STG.128 (default cache policy) ----
    // 3125 float4s; e-quad pattern repeats every 25 float4s (2 k-rows).
    // 250 active threads, stride 250 == 0 mod 25 -> q = tid%25 fixed,
    // coefficients loop-invariant. 12 full iters + tail for tid < 125.
    if (tid < 250) {
        const int q   = tid % 25;
        const int kp0 = tid / 25;               // 0..9
        const int b0  = 4 * q;                  // 0..96
        const int e0 = (b0     < EE) ? b0     : b0     - EE;
        const int e1 = (b0 + 1 < EE) ? b0 + 1 : b0 + 1 - EE;
        const int e2 = (b0 + 2 < EE) ? b0 + 2 : b0 + 2 - EE;
        const int e3 = (b0 + 3 < EE) ? b0 + 3 : b0 + 3 - EE;
        const bool r0 = (b0     >= EE);
        const bool r1 = (b0 + 1 >= EE);
        const bool r2 = (b0 + 2 >= EE);
        const bool r3 = (b0 + 3 >= EE);

        const float C0 = sC[e0], C1 = sC[e1], C2 = sC[e2], C3 = sC[e3];
        const float B0 = sB[e0], B1 = sB[e1], B2 = sB[e2], B3 = sB[e3];

        float4* __restrict__ o4 =
            (float4*)(out + (size_t)nm * (size_t)(KK * EE)
                          + (size_t)chunk * CHUNK_FLOATS);
        const float2* __restrict__ sds2 = (const float2*)sds;

        #pragma unroll
        for (int i = 0; i < 12; ++i) {
            const float2 d = sds2[kp0 + 10 * i];
            float4 v;
            v.x = fmaf(B0, r0 ? d.y : d.x, C0);
            v.y = fmaf(B1, r1 ? d.y : d.x, C1);
            v.z = fmaf(B2, r2 ? d.y : d.x, C2);
            v.w = fmaf(B3, r3 ? d.y : d.x, C3);
            o4[tid + 250 * i] = v;              // default (evict-normal) STG.128
        }
        if (tid < 125) {                        // tail: k-pairs 120..124
            const float2 d = sds2[kp0 + 120];
            float4 v;
            v.x = fmaf(B0, r0 ? d.y : d.x, C0);
            v.y = fmaf(B1, r1 ? d.y : d.x, C1);
            v.z = fmaf(B2, r2 ? d.y : d.x, C2);
            v.w = fmaf(B3, r3 ? d.y : d.x, C3);
            o4[tid + 3000] = v;
        }
    }
}

extern "C" void kernel_launch(void* const* d_in, const int* in_sizes, int n_in,
                              void* d_out, int out_size) {
    const int*   traj_loc = (const int*)  d_in[0];
    const float* poi      = (const float*)d_in[1];
    const float* vec      = (const float*)d_in[2];
    const int*   traj_len = (const int*)  d_in[3];
    const int*   cand     = (const int*)  d_in[4];
    const float* emb_su   = (const float*)d_in[5];
    const float* emb_sl   = (const float*)d_in[6];
    const float* emb_tu   = (const float*)d_in[7];
    const float* emb_tl   = (const float*)d_in[8];
    float* out = (float*)d_out;

    embed_kernel<<<NN * MM * CHUNKS, 256>>>(traj_loc, poi, vec, traj_len, cand,
                                            emb_su, emb_sl, emb_tu, emb_tl, out);
}

// round 12
// speedup vs baseline: 1.0819x; 1.0819x over previous
#include <cuda_runtime.h>
#include <math.h>
#include <stdint.h>

#define NN 32
#define MM 100
#define KK 500
#define EE 50
#define SU_C 1000.0f
#define SL_C 0.0f
#define TU_C 500.0f
#define TL_C 0.0f
#define R_EARTH_C 6371.0f
#define DEG2RAD 0.017453292519943295f

#define ROWS_PER_BLK 250                   // k-rows per block
#define CHUNKS 2                           // blocks per (n,m) tile
#define CHUNK_FLOATS (ROWS_PER_BLK * EE)   // 12500 floats = 3125 float4

__global__ __launch_bounds__(256) void embed_kernel(
    const int* __restrict__ traj_loc,   // (N, M)
    const float* __restrict__ poi,      // (LOC, 2)
    const float* __restrict__ vec,      // (N, M)
    const int* __restrict__ traj_len,   // (N,)
    const int* __restrict__ cand,       // (N, K)
    const float* __restrict__ emb_su,   // (2, E)
    const float* __restrict__ emb_sl,   // (2, E)
    const float* __restrict__ emb_tu,   // (2, E)
    const float* __restrict__ emb_tl,   // (2, E)
    float* __restrict__ out)            // (N, M, K, E)
{
    const int bid   = blockIdx.x;           // 0 .. N*M*CHUNKS-1
    const int nm    = bid >> 1;             // CHUNKS == 2
    const int chunk = bid & 1;
    const int n = nm / MM;
    const int m = nm - n * MM;
    const int tid = threadIdx.x;

    __shared__ float sC[EE];
    __shared__ float sB[EE];
    __shared__ __align__(8) float sds[ROWS_PER_BLK];

    // ---- per-(n,m) scalars ----
    const int loc1 = traj_loc[nm];
    const float2 p1 = ((const float2*)poi)[loc1];
    const float lat1 = p1.x * DEG2RAD;
    const float lon1 = p1.y * DEG2RAD;
    const float cos_lat1 = __cosf(lat1);

    const int maskv = (m < traj_len[n]) ? 1 : 0;
    const float dt = vec[nm];

    // ---- phase 1a: coefficients C[e], B[e] ----
    if (tid < EE) {
        const float esl = emb_sl[maskv * EE + tid];
        const float esu = emb_su[maskv * EE + tid];
        const float etl = emb_tl[maskv * EE + tid];
        const float etu = emb_tu[maskv * EE + tid];
        const float invS = 1.0f / (SU_C - SL_C);
        const float invT = 1.0f / (TU_C - TL_C);
        const float timev = (etl * (TU_C - dt) + etu * (dt - TL_C)) * invT;
        sC[tid] = (esl * SU_C - esu * SL_C) * invS + timev;
        sB[tid] = (esu - esl) * invS;
    }

    // ---- phase 1b: haversine for this chunk's 250 rows, all 8 warps ----
    if (tid < ROWS_PER_BLK) {
        const int k = chunk * ROWS_PER_BLK + tid;
        const int loc2 = cand[n * KK + k];
        const float2 p2 = ((const float2*)poi)[loc2];
        const float lat2 = p2.x * DEG2RAD;
        const float lon2 = p2.y * DEG2RAD;
        const float sdlat = __sinf((lat2 - lat1) * 0.5f);
        const float sdlon = __sinf((lon2 - lon1) * 0.5f);
        float a = sdlat * sdlat + cos_lat1 * __cosf(lat2) * (sdlon * sdlon);
        a = __saturatef(a);
        sds[tid] = 2.0f * R_EARTH_C * asinf(sqrtf(a));
    }
    __syncthreads();

    // ---- phase 2: outer-product write, STG.128 streaming (__stcs) ----
    // 3125 float4s; e-quad pattern repeats every 25 float4s (2 k-rows).
    // 250 active threads, stride 250 == 0 mod 25 -> q = tid%25 fixed,
    // coefficients loop-invariant in registers. 12 full iters + tail.
    if (tid < 250) {
        const int q   = tid % 25;
        const int kp0 = tid / 25;               // 0..9
        const int b0  = 4 * q;                  // 0..96
        const int e0 = (b0     < EE) ? b0     : b0     - EE;
        const int e1 = (b0 + 1 < EE) ? b0 + 1 : b0 + 1 - EE;
        const int e2 = (b0 + 2 < EE) ? b0 + 2 : b0 + 2 - EE;
        const int e3 = (b0 + 3 < EE) ? b0 + 3 : b0 + 3 - EE;
        const bool r0 = (b0     >= EE);
        const bool r1 = (b0 + 1 >= EE);
        const bool r2 = (b0 + 2 >= EE);
        const bool r3 = (b0 + 3 >= EE);

        const float C0 = sC[e0], C1 = sC[e1], C2 = sC[e2], C3 = sC[e3];
        const float B0 = sB[e0], B1 = sB[e1], B2 = sB[e2], B3 = sB[e3];

        float4* __restrict__ o4 =
            (float4*)(out + (size_t)nm * (size_t)(KK * EE)
                          + (size_t)chunk * CHUNK_FLOATS);
        const float2* __restrict__ sds2 = (const float2*)sds;

        #pragma unroll
        for (int i = 0; i < 12; ++i) {
            const float2 d = sds2[kp0 + 10 * i];
            float4 v;
            v.x = fmaf(B0, r0 ? d.y : d.x, C0);
            v.y = fmaf(B1, r1 ? d.y : d.x, C1);
            v.z = fmaf(B2, r2 ? d.y : d.x, C2);
            v.w = fmaf(B3, r3 ? d.y : d.x, C3);
            __stcs(&o4[tid + 250 * i], v);
        }
        // tail: float4 indices 3000..3124 (k-pairs 120..124)
        if (tid < 125) {
            const float2 d = sds2[kp0 + 120];
            float4 v;
            v.x = fmaf(B0, r0 ? d.y : d.x, C0);
            v.y = fmaf(B1, r1 ? d.y : d.x, C1);
            v.z = fmaf(B2, r2 ? d.y : d.x, C2);
            v.w = fmaf(B3, r3 ? d.y : d.x, C3);
            __stcs(&o4[tid + 3000], v);
        }
    }
}

extern "C" void kernel_launch(void* const* d_in, const int* in_sizes, int n_in,
                              void* d_out, int out_size) {
    const int*   traj_loc = (const int*)  d_in[0];
    const float* poi      = (const float*)d_in[1];
    const float* vec      = (const float*)d_in[2];
    const int*   traj_len = (const int*)  d_in[3];
    const int*   cand     = (const int*)  d_in[4];
    const float* emb_su   = (const float*)d_in[5];
    const float* emb_sl   = (const float*)d_in[6];
    const float* emb_tu   = (const float*)d_in[7];
    const float* emb_tl   = (const float*)d_in[8];
    float* out = (float*)d_out;

    embed_kernel<<<NN * MM * CHUNKS, 256>>>(traj_loc, poi, vec, traj_len, cand,
                                            emb_su, emb_sl, emb_tu, emb_tl, out);
}